// round 1
// baseline (speedup 1.0000x reference)
#include <cuda_runtime.h>
#include <cuda_bf16.h>
#include <cstdint>

// Shapes (fixed by setup_inputs): B=32, L=64, K=64, E=512, N=B*L=2048
#define E_DIM 512
#define K_DIM 64
#define N_MAX 2048

// Scratch (device globals; allocation-free rule)
__device__ __align__(16) float g_gv[E_DIM];     // gamma ⊙ (W1 @ w2y)
__device__ float g_Sgv;                          // sum of g_gv
__device__ __align__(16) float g_Z[N_MAX * E_DIM]; // softmax-weighted LN(y) sums

// ---------------------------------------------------------------------------
// prep1: gv[f] = gamma[f] * sum_e W1[f,e] * W2[E+e]
// grid: E_DIM blocks, 128 threads
// ---------------------------------------------------------------------------
__global__ void prep1_kernel(const float* __restrict__ W1,
                             const float* __restrict__ W2,
                             const float* __restrict__ gamma) {
    int f = blockIdx.x;
    int t = threadIdx.x;
    const float* row = W1 + (size_t)f * E_DIM;
    const float* w2y = W2 + E_DIM;
    float acc = 0.f;
    for (int j = t; j < E_DIM; j += 128)
        acc += row[j] * w2y[j];
    // warp reduce
    #pragma unroll
    for (int o = 16; o > 0; o >>= 1)
        acc += __shfl_xor_sync(0xffffffffu, acc, o);
    __shared__ float red[4];
    if ((t & 31) == 0) red[t >> 5] = acc;
    __syncthreads();
    if (t == 0) {
        float s = red[0] + red[1] + red[2] + red[3];
        g_gv[f] = gamma[f] * s;
    }
}

// prep2: S_gv = sum(gv). 1 block, 512 threads.
__global__ void prep2_kernel() {
    __shared__ float red[E_DIM];
    int t = threadIdx.x;
    red[t] = g_gv[t];
    __syncthreads();
    for (int s = 256; s > 0; s >>= 1) {
        if (t < s) red[t] += red[t + s];
        __syncthreads();
    }
    if (t == 0) g_Sgv = red[0];
}

// ---------------------------------------------------------------------------
// main kernel: one CTA per n. Stage y[n] (64x512 f32, 128KB) in smem while
// computing per-row (sum, sumsq, dot(y,gv)); softmax over k=64; weighted
// column sums -> Z[n].
//   t'[k]  = rstd_k * (dot(y_k, gv) - m_k * S_gv)     (softmax-equivalent logit)
//   p      = softmax_k(t')
//   w[k]   = p[k] * rstd[k];  C = sum_k w[k]*m[k]
//   Z[n,e] = gamma[e]*(sum_k w[k]*y[n,k,e] - C) + beta[e]
// ---------------------------------------------------------------------------
__global__ __launch_bounds__(256, 1) void attn_main_kernel(
    const float* __restrict__ y,
    const float* __restrict__ gamma,
    const float* __restrict__ beta) {
    extern __shared__ float ys[]; // [64][512] floats, 128KB
    __shared__ float s_m[K_DIM], s_rstd[K_DIM], s_t[K_DIM], s_w[K_DIM];
    __shared__ float s_C;

    const int n    = blockIdx.x;
    const int tid  = threadIdx.x;
    const int lane = tid & 31;
    const int warp = tid >> 5;

    const float Sgv = g_Sgv;

    // gv slice in registers (16 floats per lane, reused for 8 rows)
    float4 gvr[4];
    const float4* gv4 = (const float4*)g_gv;
    #pragma unroll
    for (int j = 0; j < 4; j++) gvr[j] = gv4[lane + 32 * j];

    const float4* ybase = (const float4*)(y + (size_t)n * K_DIM * E_DIM);
    float4* ys4 = (float4*)ys;

    // Phase A: each warp handles 8 rows; single pass gmem->smem + 3 reductions
    #pragma unroll
    for (int r = 0; r < 8; r++) {
        int k = warp * 8 + r;
        float s = 0.f, s2 = 0.f, dv = 0.f;
        #pragma unroll
        for (int j = 0; j < 4; j++) {
            float4 a = ybase[k * 128 + lane + 32 * j];
            ys4[k * 128 + lane + 32 * j] = a;
            s  += a.x + a.y + a.z + a.w;
            s2 += a.x * a.x + a.y * a.y + a.z * a.z + a.w * a.w;
            float4 g = gvr[j];
            dv += a.x * g.x + a.y * g.y + a.z * g.z + a.w * g.w;
        }
        #pragma unroll
        for (int o = 16; o > 0; o >>= 1) {
            s  += __shfl_xor_sync(0xffffffffu, s,  o);
            s2 += __shfl_xor_sync(0xffffffffu, s2, o);
            dv += __shfl_xor_sync(0xffffffffu, dv, o);
        }
        if (lane == 0) {
            float m    = s * (1.f / E_DIM);
            float var  = s2 * (1.f / E_DIM) - m * m;
            float rstd = rsqrtf(var + 1e-5f);
            s_m[k]    = m;
            s_rstd[k] = rstd;
            s_t[k]    = rstd * (dv - m * Sgv);
        }
    }
    __syncthreads();

    // Phase B: softmax over 64 logits in warp 0
    if (warp == 0) {
        float t0 = s_t[lane], t1 = s_t[lane + 32];
        float mx = fmaxf(t0, t1);
        #pragma unroll
        for (int o = 16; o > 0; o >>= 1)
            mx = fmaxf(mx, __shfl_xor_sync(0xffffffffu, mx, o));
        float e0 = __expf(t0 - mx), e1 = __expf(t1 - mx);
        float sum = e0 + e1;
        #pragma unroll
        for (int o = 16; o > 0; o >>= 1)
            sum += __shfl_xor_sync(0xffffffffu, sum, o);
        float inv = 1.f / sum;
        float r0 = s_rstd[lane], r1 = s_rstd[lane + 32];
        float w0 = e0 * inv * r0, w1 = e1 * inv * r1;
        s_w[lane]      = w0;
        s_w[lane + 32] = w1;
        float c = w0 * s_m[lane] + w1 * s_m[lane + 32];
        #pragma unroll
        for (int o = 16; o > 0; o >>= 1)
            c += __shfl_xor_sync(0xffffffffu, c, o);
        if (lane == 0) s_C = c;
    }
    __syncthreads();

    // Phase C: weighted column sums (each thread owns one float2 column pair)
    float2 acc = make_float2(0.f, 0.f);
    const float2* ys2 = (const float2*)ys;
    #pragma unroll 16
    for (int k = 0; k < K_DIM; k++) {
        float w = s_w[k];
        float2 v = ys2[k * 256 + tid];
        acc.x += w * v.x;
        acc.y += w * v.y;
    }
    float C = s_C;
    float2 g2 = ((const float2*)gamma)[tid];
    float2 b2 = ((const float2*)beta)[tid];
    float2 z;
    z.x = g2.x * (acc.x - C) + b2.x;
    z.y = g2.y * (acc.y - C) + b2.y;
    ((float2*)(g_Z + (size_t)n * E_DIM))[tid] = z;
}

// ---------------------------------------------------------------------------
// GEMM + epilogue: out = gelu_tanh(x + Z @ W1 + b1)
// 64x64 output tile per CTA, 256 threads (16x16), 4x4 per-thread micro-tile,
// K-tiles of 32.
// ---------------------------------------------------------------------------
__global__ __launch_bounds__(256) void gemm_gelu_kernel(
    const float* __restrict__ W1,
    const float* __restrict__ b1,
    const float* __restrict__ x,
    float* __restrict__ out) {
    __shared__ float Zs[64][33];   // padded: row stride 33 avoids bank conflicts
    __shared__ float Ws[32][64];

    const int tid  = threadIdx.x;
    const int tx   = tid & 15;
    const int ty   = tid >> 4;
    const int brow = blockIdx.y * 64;
    const int bcol = blockIdx.x * 64;

    float acc[4][4];
    #pragma unroll
    for (int i = 0; i < 4; i++)
        #pragma unroll
        for (int j = 0; j < 4; j++) acc[i][j] = 0.f;

    for (int kt = 0; kt < E_DIM; kt += 32) {
        // load Z tile: 64 rows x 32 cols (512 float4s, 2 per thread)
        #pragma unroll
        for (int l = 0; l < 2; l++) {
            int f   = tid + l * 256;
            int row = f >> 3;
            int c4  = (f & 7) * 4;
            float4 v = *(const float4*)(g_Z + (size_t)(brow + row) * E_DIM + kt + c4);
            Zs[row][c4 + 0] = v.x;
            Zs[row][c4 + 1] = v.y;
            Zs[row][c4 + 2] = v.z;
            Zs[row][c4 + 3] = v.w;
        }
        // load W1 tile: 32 rows x 64 cols
        #pragma unroll
        for (int l = 0; l < 2; l++) {
            int f   = tid + l * 256;
            int row = f >> 4;
            int c4  = (f & 15) * 4;
            float4 v = *(const float4*)(W1 + (size_t)(kt + row) * E_DIM + bcol + c4);
            *(float4*)&Ws[row][c4] = v;
        }
        __syncthreads();

        #pragma unroll
        for (int kk = 0; kk < 32; kk++) {
            float a[4];
            #pragma unroll
            for (int i = 0; i < 4; i++) a[i] = Zs[ty * 4 + i][kk];
            float4 bv = *(const float4*)&Ws[kk][tx * 4];
            float b[4] = {bv.x, bv.y, bv.z, bv.w};
            #pragma unroll
            for (int i = 0; i < 4; i++)
                #pragma unroll
                for (int j = 0; j < 4; j++)
                    acc[i][j] += a[i] * b[j];
        }
        __syncthreads();
    }

    // epilogue: gelu_tanh(x + acc + b1), vectorized float4 stores
    const int c = bcol + tx * 4;
    float4 bias = *(const float4*)(b1 + c);
    #pragma unroll
    for (int i = 0; i < 4; i++) {
        int r = brow + ty * 4 + i;
        float4 xv = *(const float4*)(x + (size_t)r * E_DIM + c);
        float u[4] = {xv.x + acc[i][0] + bias.x,
                      xv.y + acc[i][1] + bias.y,
                      xv.z + acc[i][2] + bias.z,
                      xv.w + acc[i][3] + bias.w};
        float4 o;
        float* op = &o.x;
        #pragma unroll
        for (int j = 0; j < 4; j++) {
            float uu = u[j];
            float inner = 0.7978845608028654f * (uu + 0.044715f * uu * uu * uu);
            op[j] = 0.5f * uu * (1.f + tanhf(inner));
        }
        *(float4*)(out + (size_t)r * E_DIM + c) = o;
    }
}

// ---------------------------------------------------------------------------
// kernel_launch
// input order: x, y, ln_gamma, ln_beta, W1, b1, W2, b2, select_indegree_num
// ---------------------------------------------------------------------------
extern "C" void kernel_launch(void* const* d_in, const int* in_sizes, int n_in,
                              void* d_out, int out_size) {
    const float* x     = (const float*)d_in[0];
    const float* y     = (const float*)d_in[1];
    const float* gamma = (const float*)d_in[2];
    const float* beta  = (const float*)d_in[3];
    const float* W1    = (const float*)d_in[4];
    const float* b1    = (const float*)d_in[5];
    const float* W2    = (const float*)d_in[6];
    float* out = (float*)d_out;

    const int N = in_sizes[0] / E_DIM; // 2048

    prep1_kernel<<<E_DIM, 128>>>(W1, W2, gamma);
    prep2_kernel<<<1, E_DIM>>>();

    cudaFuncSetAttribute(attn_main_kernel,
                         cudaFuncAttributeMaxDynamicSharedMemorySize,
                         K_DIM * E_DIM * (int)sizeof(float));
    attn_main_kernel<<<N, 256, K_DIM * E_DIM * sizeof(float)>>>(y, gamma, beta);

    dim3 g2(E_DIM / 64, N / 64);
    gemm_gelu_kernel<<<g2, 256>>>(W1, b1, x, out);
}

// round 5
// speedup vs baseline: 1.1835x; 1.1835x over previous
#include <cuda_runtime.h>
#include <cuda_fp16.h>
#include <cstdint>

// Shapes (fixed by setup_inputs): B=32, L=64, K=64, E=512, N=B*L=2048
#define E_DIM 512
#define K_DIM 64
#define N_MAX 2048

// Scratch (device globals; allocation-free rule)
__device__ __align__(16) float g_gv[E_DIM];        // gamma ⊙ (W1 @ w2y)
__device__ float g_Sgv;                             // sum of g_gv
__device__ __align__(16) float g_Z[N_MAX * E_DIM];  // softmax-weighted LN(y) sums

// ---------------------------------------------------------------------------
// prep1: gv[f] = gamma[f] * sum_e W1[f,e] * W2[E+e]
// ---------------------------------------------------------------------------
__global__ void prep1_kernel(const float* __restrict__ W1,
                             const float* __restrict__ W2,
                             const float* __restrict__ gamma) {
    int f = blockIdx.x;
    int t = threadIdx.x;
    const float* row = W1 + (size_t)f * E_DIM;
    const float* w2y = W2 + E_DIM;
    float acc = 0.f;
    for (int j = t; j < E_DIM; j += 128)
        acc += row[j] * w2y[j];
    #pragma unroll
    for (int o = 16; o > 0; o >>= 1)
        acc += __shfl_xor_sync(0xffffffffu, acc, o);
    __shared__ float red[4];
    if ((t & 31) == 0) red[t >> 5] = acc;
    __syncthreads();
    if (t == 0) {
        float s = red[0] + red[1] + red[2] + red[3];
        g_gv[f] = gamma[f] * s;
    }
}

// prep2: S_gv = sum(gv). 1 block, 512 threads.
__global__ void prep2_kernel() {
    __shared__ float red[E_DIM];
    int t = threadIdx.x;
    red[t] = g_gv[t];
    __syncthreads();
    for (int s = 256; s > 0; s >>= 1) {
        if (t < s) red[t] += red[t + s];
        __syncthreads();
    }
    if (t == 0) g_Sgv = red[0];
}

// ---------------------------------------------------------------------------
// main kernel: one CTA per n. Stage y[n] (64x512) in smem AS FP16 (64KB) so
// 2 CTAs co-reside per SM and pipeline load vs. softmax/weighted-sum phases.
// Stats/logits use exact fp32 values during the load pass.
//   t'[k]  = rstd_k * (dot(y_k, gv) - m_k * S_gv)
//   p      = softmax_k(t'); w[k] = p[k]*rstd[k]; C = sum_k w[k]*m[k]
//   Z[n,e] = gamma[e]*(sum_k w[k]*y[n,k,e] - C) + beta[e]
// ---------------------------------------------------------------------------
__global__ __launch_bounds__(256, 2) void attn_main_kernel(
    const float* __restrict__ y,
    const float* __restrict__ gamma,
    const float* __restrict__ beta) {
    extern __shared__ __half2 ys[]; // [64][256] half2 = 64KB
    __shared__ float s_m[K_DIM], s_rstd[K_DIM], s_t[K_DIM], s_w[K_DIM];
    __shared__ float s_C;

    const int n    = blockIdx.x;
    const int tid  = threadIdx.x;
    const int lane = tid & 31;
    const int warp = tid >> 5;

    const float Sgv = g_Sgv;

    // gv slice in registers (16 floats per lane, reused for 8 rows)
    float4 gvr[4];
    const float4* gv4 = (const float4*)g_gv;
    #pragma unroll
    for (int j = 0; j < 4; j++) gvr[j] = gv4[lane + 32 * j];

    const float4* ybase = (const float4*)(y + (size_t)n * K_DIM * E_DIM);
    uint2* ysu = (uint2*)ys; // row k: 128 uint2 (=512 halfs)

    // Phase A: each warp handles 8 rows; gmem->smem(fp16) + 3 fp32 reductions
    #pragma unroll
    for (int r = 0; r < 8; r++) {
        int k = warp * 8 + r;
        float s = 0.f, s2 = 0.f, dv = 0.f;
        #pragma unroll
        for (int j = 0; j < 4; j++) {
            float4 a = ybase[k * 128 + lane + 32 * j];
            __half2 h01 = __floats2half2_rn(a.x, a.y);
            __half2 h23 = __floats2half2_rn(a.z, a.w);
            uint32_t u01 = *reinterpret_cast<uint32_t*>(&h01);
            uint32_t u23 = *reinterpret_cast<uint32_t*>(&h23);
            ysu[k * 128 + lane + 32 * j] = make_uint2(u01, u23);
            s  += a.x + a.y + a.z + a.w;
            s2 += a.x * a.x + a.y * a.y + a.z * a.z + a.w * a.w;
            float4 g = gvr[j];
            dv += a.x * g.x + a.y * g.y + a.z * g.z + a.w * g.w;
        }
        #pragma unroll
        for (int o = 16; o > 0; o >>= 1) {
            s  += __shfl_xor_sync(0xffffffffu, s,  o);
            s2 += __shfl_xor_sync(0xffffffffu, s2, o);
            dv += __shfl_xor_sync(0xffffffffu, dv, o);
        }
        if (lane == 0) {
            float m    = s * (1.f / E_DIM);
            float var  = s2 * (1.f / E_DIM) - m * m;
            float rstd = rsqrtf(var + 1e-5f);
            s_m[k]    = m;
            s_rstd[k] = rstd;
            s_t[k]    = rstd * (dv - m * Sgv);
        }
    }
    __syncthreads();

    // Phase B: softmax over 64 logits in warp 0
    if (warp == 0) {
        float t0 = s_t[lane], t1 = s_t[lane + 32];
        float mx = fmaxf(t0, t1);
        #pragma unroll
        for (int o = 16; o > 0; o >>= 1)
            mx = fmaxf(mx, __shfl_xor_sync(0xffffffffu, mx, o));
        float e0 = __expf(t0 - mx), e1 = __expf(t1 - mx);
        float sum = e0 + e1;
        #pragma unroll
        for (int o = 16; o > 0; o >>= 1)
            sum += __shfl_xor_sync(0xffffffffu, sum, o);
        float inv = 1.f / sum;
        float r0 = s_rstd[lane], r1 = s_rstd[lane + 32];
        float w0 = e0 * inv * r0, w1 = e1 * inv * r1;
        s_w[lane]      = w0;
        s_w[lane + 32] = w1;
        float c = w0 * s_m[lane] + w1 * s_m[lane + 32];
        #pragma unroll
        for (int o = 16; o > 0; o >>= 1)
            c += __shfl_xor_sync(0xffffffffu, c, o);
        if (lane == 0) s_C = c;
    }
    __syncthreads();

    // Phase C: weighted column sums (each thread owns one half2 column pair)
    float2 acc = make_float2(0.f, 0.f);
    #pragma unroll 16
    for (int k = 0; k < K_DIM; k++) {
        float w = s_w[k];
        float2 v = __half22float2(ys[k * 256 + tid]);
        acc.x += w * v.x;
        acc.y += w * v.y;
    }
    float C = s_C;
    float2 g2 = ((const float2*)gamma)[tid];
    float2 b2 = ((const float2*)beta)[tid];
    float2 z;
    z.x = g2.x * (acc.x - C) + b2.x;
    z.y = g2.y * (acc.y - C) + b2.y;
    ((float2*)(g_Z + (size_t)n * E_DIM))[tid] = z;
}

// ---------------------------------------------------------------------------
// GEMM + epilogue: out = gelu_tanh(x + Z @ W1 + b1)
// BM=128, BN=64, BK=32, 256 threads (16x16), 8x4 micro-tile.
// Z stored k-major in smem (transposed on load) so a-frags are 2x LDS.128.
// Register prefetch of next k-tile hides L2 latency. Grid = 128 CTAs = 1 wave.
// ---------------------------------------------------------------------------
#define BM 128
#define BN 64
#define BK 32
#define ZS_STRIDE 132  // BM + 4 pad (multiple of 4 keeps float4 alignment)

__global__ __launch_bounds__(256) void gemm_gelu_kernel(
    const float* __restrict__ W1,
    const float* __restrict__ b1,
    const float* __restrict__ x,
    float* __restrict__ out) {
    __shared__ float Zs[BK * ZS_STRIDE]; // k-major: Zs[kk][m]
    __shared__ float Ws[BK][BN];         // k-major: Ws[kk][nn]

    const int tid  = threadIdx.x;
    const int tx   = tid & 15;   // n-group: cols tx*4..+3
    const int ty   = tid >> 4;   // m-group: rows ty*8..+7
    const int brow = blockIdx.y * BM;
    const int bcol = blockIdx.x * BN;

    // gmem load mappings
    const int zm  = tid >> 3;          // 0..31 (+32 per l)
    const int zk4 = (tid & 7) * 4;     // 0,4,..28
    const int wr  = tid >> 4;          // 0..15 (+16 per l)
    const int wc4 = (tid & 15) * 4;

    float4 zf[4]; // Z tile frags: rows zm + 32*l (4 frags cover 128 rows)
    float4 wf[2];

    // prefetch kt = 0
    #pragma unroll
    for (int l = 0; l < 4; l++)
        zf[l] = *(const float4*)(g_Z + (size_t)(brow + zm + 32 * l) * E_DIM + zk4);
    #pragma unroll
    for (int l = 0; l < 2; l++)
        wf[l] = *(const float4*)(W1 + (size_t)(wr + 16 * l) * E_DIM + bcol + wc4);

    float acc[8][4];
    #pragma unroll
    for (int i = 0; i < 8; i++)
        #pragma unroll
        for (int j = 0; j < 4; j++) acc[i][j] = 0.f;

    for (int kt = 0; kt < E_DIM; kt += BK) {
        // store prefetched frags to smem (Z transposed to k-major)
        #pragma unroll
        for (int l = 0; l < 4; l++) {
            int m = zm + 32 * l;
            Zs[(zk4 + 0) * ZS_STRIDE + m] = zf[l].x;
            Zs[(zk4 + 1) * ZS_STRIDE + m] = zf[l].y;
            Zs[(zk4 + 2) * ZS_STRIDE + m] = zf[l].z;
            Zs[(zk4 + 3) * ZS_STRIDE + m] = zf[l].w;
        }
        #pragma unroll
        for (int l = 0; l < 2; l++)
            *(float4*)&Ws[wr + 16 * l][wc4] = wf[l];
        __syncthreads();

        // prefetch next k-tile while computing this one
        if (kt + BK < E_DIM) {
            #pragma unroll
            for (int l = 0; l < 4; l++)
                zf[l] = *(const float4*)(g_Z + (size_t)(brow + zm + 32 * l) * E_DIM + kt + BK + zk4);
            #pragma unroll
            for (int l = 0; l < 2; l++)
                wf[l] = *(const float4*)(W1 + (size_t)(kt + BK + wr + 16 * l) * E_DIM + bcol + wc4);
        }

        #pragma unroll
        for (int kk = 0; kk < BK; kk++) {
            float4 a0 = *(const float4*)&Zs[kk * ZS_STRIDE + ty * 8];
            float4 a1 = *(const float4*)&Zs[kk * ZS_STRIDE + ty * 8 + 4];
            float4 bv = *(const float4*)&Ws[kk][tx * 4];
            float a[8] = {a0.x, a0.y, a0.z, a0.w, a1.x, a1.y, a1.z, a1.w};
            float b[4] = {bv.x, bv.y, bv.z, bv.w};
            #pragma unroll
            for (int i = 0; i < 8; i++)
                #pragma unroll
                for (int j = 0; j < 4; j++)
                    acc[i][j] += a[i] * b[j];
        }
        __syncthreads();
    }

    // epilogue: gelu_tanh(x + acc + b1) via fast exp: tanh(t) = 1 - 2/(e^{2t}+1)
    const int c = bcol + tx * 4;
    float4 bias = *(const float4*)(b1 + c);
    #pragma unroll
    for (int i = 0; i < 8; i++) {
        int r = brow + ty * 8 + i;
        float4 xv = *(const float4*)(x + (size_t)r * E_DIM + c);
        float u[4] = {xv.x + acc[i][0] + bias.x,
                      xv.y + acc[i][1] + bias.y,
                      xv.z + acc[i][2] + bias.z,
                      xv.w + acc[i][3] + bias.w};
        float4 o;
        float* op = &o.x;
        #pragma unroll
        for (int j = 0; j < 4; j++) {
            float uu = u[j];
            float inner = 0.7978845608028654f * (uu + 0.044715f * uu * uu * uu);
            float t = 1.f - 2.f / (__expf(2.f * inner) + 1.f);
            op[j] = 0.5f * uu * (1.f + t);
        }
        *(float4*)(out + (size_t)r * E_DIM + c) = o;
    }
}

// ---------------------------------------------------------------------------
// kernel_launch
// input order: x, y, ln_gamma, ln_beta, W1, b1, W2, b2, select_indegree_num
// ---------------------------------------------------------------------------
extern "C" void kernel_launch(void* const* d_in, const int* in_sizes, int n_in,
                              void* d_out, int out_size) {
    const float* x     = (const float*)d_in[0];
    const float* y     = (const float*)d_in[1];
    const float* gamma = (const float*)d_in[2];
    const float* beta  = (const float*)d_in[3];
    const float* W1    = (const float*)d_in[4];
    const float* b1    = (const float*)d_in[5];
    const float* W2    = (const float*)d_in[6];
    float* out = (float*)d_out;

    const int N = in_sizes[0] / E_DIM; // 2048

    prep1_kernel<<<E_DIM, 128>>>(W1, W2, gamma);
    prep2_kernel<<<1, E_DIM>>>();

    const int smem_bytes = K_DIM * E_DIM * (int)sizeof(__half); // 64KB
    cudaFuncSetAttribute(attn_main_kernel,
                         cudaFuncAttributeMaxDynamicSharedMemorySize, smem_bytes);
    attn_main_kernel<<<N, 256, smem_bytes>>>(y, gamma, beta);

    dim3 g2(E_DIM / BN, N / BM);
    gemm_gelu_kernel<<<g2, 256>>>(W1, b1, x, out);
}